// round 15
// baseline (speedup 1.0000x reference)
#include <cuda_runtime.h>
#include <math.h>

#define D      128
#define BMAX   1024
#define SUB    1024
#define GRID1  444      // 3 blocks/SM x 148 SMs: single wave, no raggedness

// Scratch: [0, BMAX*D) per-segment sums; [BMAX*D, +BMAX) counts (float).
// .bss => zero at load. k2 re-zeroes exactly what it consumed (rows are
// block-exclusive), so scratch is zero again before every graph replay.
__device__ float g_buf[BMAX * D + BMAX];

// softplus with the reference's Threshold(-50, 50) folding
__device__ __forceinline__ float softplus_thresh(float v) {
    float sp = fmaxf(v, 0.0f) + log1pf(expf(-fabsf(v)));
    return sp < 50.0f ? sp : -50.0f;
}

// ---------------------------------------------------------------------------
// Kernel 1 (persistent, single wave): per-segment sum of (|x|+eps)^p
// (p = ps0 for d<64, ps1 for d>=64) + node counts over a contiguous
// ~N/444 span per block, iterated in SUB-node sub-chunks.
// batch sorted -> register runs + atomic flush on boundary.
// 256 threads = 32 feature-quads (tx) x 8 node lanes (ty). Rolling pipeline
// (next 4 LDG.128 issued before current pow chain); .cs streaming.
// ---------------------------------------------------------------------------
__global__ void __launch_bounds__(256, 3)
k1_pool(const float* __restrict__ x, const void* __restrict__ batch,
        const float* __restrict__ ps_raw, int N)
{
    __shared__ int sseg[SUB];     // 4 KB

    const int tid = threadIdx.x;
    const int tx  = tid & 31;   // feature quad: features [4*tx, 4*tx+3]
    const int ty  = tid >> 5;   // node lane 0..7

    const long long lo = (long long)blockIdx.x * N / GRID1;
    const long long hi = (long long)(blockIdx.x + 1) * N / GRID1;

    // detect int32 vs int64 batch dtype (uniform across grid):
    // u64 at even idx ~N/4: int64 buffer -> small value; int32 -> >= 2^32
    const unsigned long long* p64b = (const unsigned long long*)batch;
    size_t q = ((size_t)(N >> 2)) & ~(size_t)1;
    const bool is64 = (p64b[q] < (1ull << 20));

    const float p = softplus_thresh(ps_raw[tx >> 4]);
    float* __restrict__ cntf = g_buf + BMAX * D;

    float ax = 0.f, ay = 0.f, az = 0.f, aw = 0.f;
    int cur = -1;
    int cnt = 0;

#define ACC4(v)                                   \
    ax += __powf(fabsf((v).x) + 1e-6f, p);        \
    ay += __powf(fabsf((v).y) + 1e-6f, p);        \
    az += __powf(fabsf((v).z) + 1e-6f, p);        \
    aw += __powf(fabsf((v).w) + 1e-6f, p);

#define FLUSH()                                                   \
    if (cnt > 0) {                                                \
        float* s = &g_buf[cur * D + tx * 4];                      \
        atomicAdd(s + 0, ax); atomicAdd(s + 1, ay);               \
        atomicAdd(s + 2, az); atomicAdd(s + 3, aw);               \
        if (tx == 0) atomicAdd(&cntf[cur], (float)cnt);           \
        ax = ay = az = aw = 0.f; cnt = 0;                         \
    }

#define PROC(v, b)                                \
    if ((b) != cur) { FLUSH(); cur = (b); }       \
    ACC4(v); cnt++;

    for (long long base = lo; base < hi; base += SUB) {
        const int len = (int)(hi - base < SUB ? hi - base : SUB);
        __syncthreads();             // protect sseg reuse across sub-chunks
        if (is64) {
            const long long* bb = (const long long*)batch;
            for (int i = tid; i < len; i += 256) sseg[i] = (int)bb[base + i];
        } else {
            const int* bb = (const int*)batch;
            for (int i = tid; i < len; i += 256) sseg[i] = bb[base + i];
        }
        __syncthreads();

        const float4* __restrict__ x4 = (const float4*)x + base * 32 + tx;

        int j = ty;
        bool have = (j + 24 < len);
        float4 v0, v1, v2, v3;
        if (have) {
            v0 = __ldcs(&x4[(size_t)(j)      * 32]);
            v1 = __ldcs(&x4[(size_t)(j + 8)  * 32]);
            v2 = __ldcs(&x4[(size_t)(j + 16) * 32]);
            v3 = __ldcs(&x4[(size_t)(j + 24) * 32]);
        }
        while (have) {
            const int jn = j + 32;
            const bool haven = (jn + 24 < len);
            float4 n0, n1, n2, n3;
            if (haven) {                 // prefetch next iteration (MLP ~8)
                n0 = __ldcs(&x4[(size_t)(jn)      * 32]);
                n1 = __ldcs(&x4[(size_t)(jn + 8)  * 32]);
                n2 = __ldcs(&x4[(size_t)(jn + 16) * 32]);
                n3 = __ldcs(&x4[(size_t)(jn + 24) * 32]);
            }
            int b0s = sseg[j];
            int b3s = sseg[j + 24];
            if (b0s == cur && b3s == cur) {  // sorted: ends equal => all 4
                ACC4(v0); ACC4(v1); ACC4(v2); ACC4(v3);
                cnt += 4;
            } else {
                int b1s = sseg[j + 8];
                int b2s = sseg[j + 16];
                PROC(v0, b0s); PROC(v1, b1s); PROC(v2, b2s); PROC(v3, b3s);
            }
            v0 = n0; v1 = n1; v2 = n2; v3 = n3;
            j = jn; have = haven;
        }
        for (; j < len; j += 8) {            // tail of sub-chunk
            float4 v = __ldcs(&x4[(size_t)j * 32]);
            int b = sseg[j];
            PROC(v, b);
        }
    }
    FLUSH();

#undef PROC
#undef FLUSH
#undef ACC4
}

// ---------------------------------------------------------------------------
// Kernel 2 (R13-PROVEN, 9.2us): gnp = s^(1/p) * n^(-qs0);
// out = gnp @ W^T + bias.  Grid 256 x 256 thr, 4 graph rows/block, W staged
// in TWO K=64 halves (float4, stride-17 pad -> conflict-free LDS.128).
// o = tid&127 output col; g = tid>>7 -> rows {2g, 2g+1}; split accumulators.
// Scratch re-zero = fire-and-forget STG loop AFTER the gs head's sync
// (drains under the staging/FFMA section, free).
// ---------------------------------------------------------------------------
__global__ void __launch_bounds__(256)
k2_gemm(const float* __restrict__ W, const float* __restrict__ bias,
        const float* __restrict__ ps_raw, const float* __restrict__ qs_raw,
        float* __restrict__ out)
{
    __shared__ float w[128 * 68];     // 34.8 KB
    __shared__ float gs[4 * 128];     // 2 KB

    const int tid = threadIdx.x;
    const int o   = tid & 127;
    const int g   = tid >> 7;         // 0/1 -> rows {2g, 2g+1}
    const int b0  = blockIdx.x * 4;

    const float qs0 = tanhf(qs_raw[0]);
    float* __restrict__ cntf = g_buf + BMAX * D;

    // head: pure read -> pow -> smem (no stores mixed in)
    for (int idx = tid; idx < 512; idx += 256) {
        int r = idx >> 7, d = idx & 127;
        float pp = softplus_thresh(ps_raw[d >> 6]);
        float s = g_buf[(b0 + r) * D + d];
        float n = cntf[b0 + r];
        gs[idx] = __powf(s, 1.0f / pp) * __powf(n, -qs0);
    }
    __syncthreads();

    // fire-and-forget scratch re-zero (block-exclusive rows: 128 float4 by
    // threads 0..127; counts by 128..131). Drains under staging/FFMA below.
    if (tid < 128) {
        float4* gb4 = (float4*)(g_buf + (size_t)b0 * D);
        gb4[tid] = make_float4(0.f, 0.f, 0.f, 0.f);
    } else if (tid < 132) {
        cntf[b0 + (tid - 128)] = 0.f;
    }

    // split accumulators: chain length halved, ILP doubled
    float a0 = bias[o], c0 = 0.f;     // row 2g
    float a1 = bias[o], c1 = 0.f;     // row 2g+1

    const float4* __restrict__ W4 = (const float4*)W;
    float4* w4 = (float4*)w;
    const float4* gs4 = (const float4*)gs;

    #pragma unroll
    for (int half = 0; half < 2; half++) {
        if (half) __syncthreads();
        // stage W[:, half*64 .. +63]: 128 rows x 16 float4, 8 per thread
        for (int idx = tid; idx < 128 * 16; idx += 256) {
            int o2 = idx >> 4, dk4 = idx & 15;
            w4[o2 * 17 + dk4] = W4[o2 * 32 + half * 16 + dk4];
        }
        __syncthreads();

        #pragma unroll
        for (int dk4 = 0; dk4 < 16; dk4++) {
            float4 wv = w4[o * 17 + dk4];            // conflict-free LDS.128
            int d4 = half * 16 + dk4;
            float4 g0 = gs4[(g * 2)     * 32 + d4];  // warp-uniform broadcast
            float4 g1 = gs4[(g * 2 + 1) * 32 + d4];
            a0 += g0.x * wv.x; c0 += g0.z * wv.z;    // independent chains
            a0 += g0.y * wv.y; c0 += g0.w * wv.w;
            a1 += g1.x * wv.x; c1 += g1.z * wv.z;
            a1 += g1.y * wv.y; c1 += g1.w * wv.w;
        }
    }

    out[(size_t)(b0 + g * 2)     * D + o] = a0 + c0;
    out[(size_t)(b0 + g * 2 + 1) * D + o] = a1 + c1;
}

// ---------------------------------------------------------------------------
extern "C" void kernel_launch(void* const* d_in, const int* in_sizes, int n_in,
                              void* d_out, int out_size)
{
    const float* x      = (const float*)d_in[0];
    const void*  batch  = d_in[1];
    const float* ps_raw = (const float*)d_in[2];
    const float* qs_raw = (const float*)d_in[3];
    const float* W      = (const float*)d_in[4];
    const float* bias   = (const float*)d_in[5];
    float*       out    = (float*)d_out;

    const int N = in_sizes[0] / D;    // node count from x (dtype-proof)
    const int B = out_size / D;       // 1024

    k1_pool<<<GRID1, 256>>>(x, batch, ps_raw, N);
    k2_gemm<<<B / 4, 256>>>(W, bias, ps_raw, qs_raw, out);
}

// round 16
// speedup vs baseline: 1.0175x; 1.0175x over previous
#include <cuda_runtime.h>
#include <math.h>

#define D      128
#define BMAX   1024
#define CHUNK  512
#define W_F4_STRIDE 33                       // float4 stride: conflict-free
#define K2_DSMEM (128 * W_F4_STRIDE * 16)    // 67584 B dynamic smem

// Scratch: [0, BMAX*D) per-segment sums; [BMAX*D, +BMAX) counts (float).
// .bss => zero at load. k2 re-zeroes exactly what it consumed (rows are
// block-exclusive), so scratch is zero again before every graph replay.
__device__ float g_buf[BMAX * D + BMAX];

// softplus with the reference's Threshold(-50, 50) folding
__device__ __forceinline__ float softplus_thresh(float v) {
    float sp = fmaxf(v, 0.0f) + log1pf(expf(-fabsf(v)));
    return sp < 50.0f ? sp : -50.0f;
}

// ---------------------------------------------------------------------------
// Kernel 1 (R13-PROVEN, ~41us, ~78% of HBM spec = practical ceiling):
// per-segment sum of (|x|+eps)^p (p = ps0 for d<64, ps1 for d>=64) + counts.
// batch sorted -> register runs + atomic flush on boundary.
// 256 threads = 32 feature-quads (tx) x 8 node lanes (ty). Rolling pipeline
// (next 4 LDG.128 issued before current pow chain); .cs streaming.
// ---------------------------------------------------------------------------
__global__ void __launch_bounds__(256)
k1_pool(const float* __restrict__ x, const void* __restrict__ batch,
        const float* __restrict__ ps_raw, int N)
{
    __shared__ int sseg[CHUNK];

    const int tid = threadIdx.x;
    const int tx  = tid & 31;   // feature quad: features [4*tx, 4*tx+3]
    const int ty  = tid >> 5;   // node lane 0..7

    const long long start = (long long)blockIdx.x * CHUNK;
    const int len = (int)min((long long)CHUNK, (long long)N - start);

    // detect int32 vs int64 batch dtype (uniform across grid):
    // u64 at even idx ~N/4: int64 buffer -> small value; int32 -> >= 2^32
    const unsigned long long* p64b = (const unsigned long long*)batch;
    size_t q = ((size_t)(N >> 2)) & ~(size_t)1;
    const bool is64 = (p64b[q] < (1ull << 20));

    if (is64) {
        const long long* bb = (const long long*)batch;
        for (int i = tid; i < len; i += 256) sseg[i] = (int)bb[start + i];
    } else {
        const int* bb = (const int*)batch;
        for (int i = tid; i < len; i += 256) sseg[i] = bb[start + i];
    }
    __syncthreads();

    const float p = softplus_thresh(ps_raw[tx >> 4]);

    const float4* __restrict__ x4 = (const float4*)x + (size_t)start * 32 + tx;
    float* __restrict__ cntf = g_buf + BMAX * D;

    float ax = 0.f, ay = 0.f, az = 0.f, aw = 0.f;
    int cur = -1;
    int cnt = 0;

#define ACC4(v)                                   \
    ax += __powf(fabsf((v).x) + 1e-6f, p);        \
    ay += __powf(fabsf((v).y) + 1e-6f, p);        \
    az += __powf(fabsf((v).z) + 1e-6f, p);        \
    aw += __powf(fabsf((v).w) + 1e-6f, p);

#define FLUSH()                                                   \
    if (cnt > 0) {                                                \
        float* s = &g_buf[cur * D + tx * 4];                      \
        atomicAdd(s + 0, ax); atomicAdd(s + 1, ay);               \
        atomicAdd(s + 2, az); atomicAdd(s + 3, aw);               \
        if (tx == 0) atomicAdd(&cntf[cur], (float)cnt);           \
        ax = ay = az = aw = 0.f; cnt = 0;                         \
    }

#define PROC(v, b)                                \
    if ((b) != cur) { FLUSH(); cur = (b); }       \
    ACC4(v); cnt++;

    int j = ty;
    bool have = (j + 24 < len);
    float4 v0, v1, v2, v3;
    if (have) {
        v0 = __ldcs(&x4[(size_t)(j)      * 32]);
        v1 = __ldcs(&x4[(size_t)(j + 8)  * 32]);
        v2 = __ldcs(&x4[(size_t)(j + 16) * 32]);
        v3 = __ldcs(&x4[(size_t)(j + 24) * 32]);
    }
    while (have) {
        const int jn = j + 32;
        const bool haven = (jn + 24 < len);
        float4 n0, n1, n2, n3;
        if (haven) {                     // prefetch next iteration (MLP ~8)
            n0 = __ldcs(&x4[(size_t)(jn)      * 32]);
            n1 = __ldcs(&x4[(size_t)(jn + 8)  * 32]);
            n2 = __ldcs(&x4[(size_t)(jn + 16) * 32]);
            n3 = __ldcs(&x4[(size_t)(jn + 24) * 32]);
        }
        int b0 = sseg[j];
        int b3 = sseg[j + 24];
        if (b0 == cur && b3 == cur) {    // sorted: b0==b3 => all 4 equal
            ACC4(v0); ACC4(v1); ACC4(v2); ACC4(v3);
            cnt += 4;
        } else {
            int b1 = sseg[j + 8];
            int b2 = sseg[j + 16];
            PROC(v0, b0); PROC(v1, b1); PROC(v2, b2); PROC(v3, b3);
        }
        v0 = n0; v1 = n1; v2 = n2; v3 = n3;
        j = jn; have = haven;
    }
    for (; j < len; j += 8) {            // tail
        float4 v = __ldcs(&x4[(size_t)j * 32]);
        int b = sseg[j];
        PROC(v, b);
    }
    FLUSH();

#undef PROC
#undef FLUSH
#undef ACC4
}

// ---------------------------------------------------------------------------
// Kernel 2 (single-stage, dynamic smem): gnp = s^(1/p) * n^(-qs0);
// out = gnp @ W^T + bias.  Grid 256 x 256 thr, 4 graph rows/block.
// ALL of W (128 x 128) staged ONCE into 67.6KB dynamic smem (float4 rows,
// stride-33 pad -> conflict-free LDS.128/STS.128), CONCURRENT with the gs
// head (both complete before ONE barrier). Then an uninterrupted 32-iter
// FFMA loop. Barriers: 4 -> 1. Scratch re-zero = fire-and-forget after the
// barrier (drains under FFMA, free).
// ---------------------------------------------------------------------------
__global__ void __launch_bounds__(256)
k2_gemm(const float* __restrict__ W, const float* __restrict__ bias,
        const float* __restrict__ ps_raw, const float* __restrict__ qs_raw,
        float* __restrict__ out)
{
    extern __shared__ float wdyn[];   // 128 * 132 floats = 67.6 KB
    __shared__ float gs[4 * 128];     // 2 KB static

    const int tid = threadIdx.x;
    const int o   = tid & 127;
    const int g   = tid >> 7;         // 0/1 -> rows {2g, 2g+1}
    const int b0  = blockIdx.x * 4;

    const float4* __restrict__ W4 = (const float4*)W;
    float4* w4 = (float4*)wdyn;

    // ---- stage ALL of W: 128 rows x 32 float4, 16 per thread (MLP 16) ----
    #pragma unroll 4
    for (int idx = tid; idx < 128 * 32; idx += 256) {
        int o2 = idx >> 5, c = idx & 31;
        w4[o2 * W_F4_STRIDE + c] = W4[o2 * 32 + c];
    }

    // ---- gs head (overlaps the staging LDGs; no stores mixed in) ----
    const float qs0 = tanhf(qs_raw[0]);
    float* __restrict__ cntf = g_buf + BMAX * D;
    for (int idx = tid; idx < 512; idx += 256) {
        int r = idx >> 7, d = idx & 127;
        float pp = softplus_thresh(ps_raw[d >> 6]);
        float s = g_buf[(b0 + r) * D + d];
        float n = cntf[b0 + r];
        gs[idx] = __powf(s, 1.0f / pp) * __powf(n, -qs0);
    }

    __syncthreads();                  // the ONLY barrier

    // fire-and-forget scratch re-zero (block-exclusive rows: 128 float4 by
    // threads 0..127; counts by 128..131). Drains under the FFMA below.
    if (tid < 128) {
        float4* gb4 = (float4*)(g_buf + (size_t)b0 * D);
        gb4[tid] = make_float4(0.f, 0.f, 0.f, 0.f);
    } else if (tid < 132) {
        cntf[b0 + (tid - 128)] = 0.f;
    }

    // split accumulators: chain length halved, ILP doubled
    float a0 = bias[o], c0 = 0.f;     // row 2g
    float a1 = bias[o], c1 = 0.f;     // row 2g+1

    const float4* gs4 = (const float4*)gs;
    const float4* wrow = w4 + o * W_F4_STRIDE;
    const float4* gsa  = gs4 + (g * 2) * 32;
    const float4* gsb  = gs4 + (g * 2 + 1) * 32;

    #pragma unroll
    for (int dk4 = 0; dk4 < 32; dk4++) {
        float4 wv = wrow[dk4];        // conflict-free LDS.128
        float4 g0 = gsa[dk4];         // warp-uniform broadcast
        float4 g1 = gsb[dk4];
        a0 += g0.x * wv.x; c0 += g0.z * wv.z;    // independent chains
        a0 += g0.y * wv.y; c0 += g0.w * wv.w;
        a1 += g1.x * wv.x; c1 += g1.z * wv.z;
        a1 += g1.y * wv.y; c1 += g1.w * wv.w;
    }

    out[(size_t)(b0 + g * 2)     * D + o] = a0 + c0;
    out[(size_t)(b0 + g * 2 + 1) * D + o] = a1 + c1;
}

// ---------------------------------------------------------------------------
extern "C" void kernel_launch(void* const* d_in, const int* in_sizes, int n_in,
                              void* d_out, int out_size)
{
    const float* x      = (const float*)d_in[0];
    const void*  batch  = d_in[1];
    const float* ps_raw = (const float*)d_in[2];
    const float* qs_raw = (const float*)d_in[3];
    const float* W      = (const float*)d_in[4];
    const float* bias   = (const float*)d_in[5];
    float*       out    = (float*)d_out;

    const int N = in_sizes[0] / D;    // node count from x (dtype-proof)
    const int B = out_size / D;       // 1024

    // not a stream op; deterministic on every call; capture-safe
    cudaFuncSetAttribute(k2_gemm, cudaFuncAttributeMaxDynamicSharedMemorySize,
                         K2_DSMEM);

    const int grid1 = (N + CHUNK - 1) / CHUNK;
    k1_pool<<<grid1, 256>>>(x, batch, ps_raw, N);
    k2_gemm<<<B / 4, 256, K2_DSMEM>>>(W, bias, ps_raw, qs_raw, out);
}